// round 16
// baseline (speedup 1.0000x reference)
#include <cuda_runtime.h>
#include <cuda_fp16.h>
#include <cfloat>
#include <cstdint>

#define DIM      768
#define QN       64
#define TILE_M   128
#define CHUNK_K  64
#define NCHUNK   (DIM / CHUNK_K)     // 12
#define KSTEPS   (CHUNK_K / 16)      // 4
#define NTHREADS 256
#define NBLOCKS  304                 // 2 per SM x 152 SMs
#define TOPC     16                  // pass-1 per-block candidates per query
#define TOPK     5
#define MARGIN   4.0f                // > 2x hard bound on |s3term - s_hh|

// ---- smem layout: [B buf0 8KB][B buf1 8KB][stage 34.8KB] ----
#define B_SPLIT   8192                          // hi-split tile: 64 k-rows x 128B SW128
#define OFF_STAGE (2 * B_SPLIT)                 // 16384
#define STAGE_STRIDE 68
#define STAGE_BYTES  (TILE_M * STAGE_STRIDE * 4)   // 34816
#define SMEM_DYN  (OFF_STAGE + STAGE_BYTES + 1024) // 52224/CTA; 2 CTAs ~ 104KB

// ---------------- device scratch (no allocations allowed) ----------------
__device__ uint4 g_qswh4[NCHUNK * B_SPLIT / 16];   // hi-split pre-swizzled per-chunk images
__device__ float g_qf[QN * DIM];                   // exact fp32 projected queries (pass 2)
__device__ float g_cand_val[NBLOCKS * QN * TOPC];
__device__ int   g_cand_idx[NBLOCKS * QN * TOPC];

// ---------------- helpers ----------------
__device__ __forceinline__ uint32_t smem_u32(const void* p) {
    uint32_t a;
    asm("{ .reg .u64 t; cvta.to.shared.u64 t, %1; cvt.u32.u64 %0, t; }" : "=r"(a) : "l"(p));
    return a;
}
#define SW128(off) ((off) ^ (((off) >> 3) & 0x70))

__device__ __forceinline__ void ldsm_x4_t(uint32_t* r, uint32_t addr) {
    asm volatile("ldmatrix.sync.aligned.m8n8.x4.trans.shared.b16 {%0,%1,%2,%3}, [%4];"
        : "=r"(r[0]), "=r"(r[1]), "=r"(r[2]), "=r"(r[3]) : "r"(addr));
}
__device__ __forceinline__ void mma_fp16(float* d, const uint32_t* a, const uint32_t* b) {
    asm volatile("mma.sync.aligned.m16n8k16.row.col.f32.f16.f16.f32 "
        "{%0,%1,%2,%3}, {%4,%5,%6,%7}, {%8,%9}, {%0,%1,%2,%3};"
        : "+f"(d[0]), "+f"(d[1]), "+f"(d[2]), "+f"(d[3])
        : "r"(a[0]), "r"(a[1]), "r"(a[2]), "r"(a[3]), "r"(b[0]), "r"(b[1]));
}

// strict ordering: higher value wins; ties -> lower index (matches lax.top_k)
__device__ __forceinline__ bool better(float av, int ai, float bv, int bi) {
    return (av > bv) || (av == bv && ai < bi);
}
template <int K>
__device__ __forceinline__ void topk_insert(float* tv, int* ti, float s, int idx) {
    if (!better(s, idx, tv[K - 1], ti[K - 1])) return;
    int pos = K - 1;
    #pragma unroll
    for (int it = 0; it < K - 1; it++) {
        if (pos > 0 && better(s, idx, tv[pos - 1], ti[pos - 1])) {
            tv[pos] = tv[pos - 1]; ti[pos] = ti[pos - 1]; pos--;
        }
    }
    tv[pos] = s; ti[pos] = idx;
}

// issue cp.async for one hi-split B chunk image (8KB, 2x16B per thread)
__device__ __forceinline__ void issue_B(uint32_t bufS, int chunk, int tid) {
    const char* src = (const char*)g_qswh4 + (size_t)chunk * B_SPLIT;
    #pragma unroll
    for (int j = 0; j < 2; j++) {
        uint32_t dst = bufS + (uint32_t)((tid + j * NTHREADS) * 16);
        asm volatile("cp.async.ca.shared.global [%0], [%1], 16;"
                     :: "r"(dst), "l"(src + (tid + j * NTHREADS) * 16));
    }
}

// per-lane A fragment fp32 load: rows {r0,r0+8}, col pairs {c0,c0+8}
__device__ __forceinline__ void ldgA(float2* f, const float* __restrict__ emb,
                                     int docbase, int k0, int ndocs,
                                     int w, int gr, int gc) {
    int r0 = docbase + w * 16 + gr;
    int r1 = r0 + 8;
    const float* p0 = emb + (size_t)r0 * DIM + k0 + gc;
    const float* p1 = emb + (size_t)r1 * DIM + k0 + gc;
    float2 z = make_float2(0.f, 0.f);
    f[0] = (r0 < ndocs) ? __ldcg((const float2*)p0)       : z;
    f[1] = (r1 < ndocs) ? __ldcg((const float2*)p1)       : z;
    f[2] = (r0 < ndocs) ? __ldcg((const float2*)(p0 + 8)) : z;
    f[3] = (r1 < ndocs) ? __ldcg((const float2*)(p1 + 8)) : z;
}
// pack fp32 fragment pairs -> hi fp16 fragment regs (rn)
__device__ __forceinline__ void packA(const float2* f, uint32_t* Ahi) {
    #pragma unroll
    for (int j = 0; j < 4; j++) {
        __half2 h = __floats2half2_rn(f[j].x, f[j].y);
        Ahi[j] = *(const uint32_t*)&h;
    }
}

// ---------------- kernel 1: q = query @ W^T + b -> fp32 q + hi-split swizzled tiles ----------------
#define QP_KC 64
#define QP_ROWS 8
__global__ __launch_bounds__(256) void qproj_kernel(
    const float* __restrict__ query, const float* __restrict__ W, const float* __restrict__ bias)
{
    __shared__ float sW[QP_ROWS][QP_KC];
    __shared__ float sQ[QN][QP_KC + 1];

    int tid = threadIdx.x;
    int dbase = blockIdx.x * QP_ROWS;
    int q  = tid & 63;
    int dg = tid >> 6;

    float acc[2] = {0.f, 0.f};

    for (int kb = 0; kb < DIM; kb += QP_KC) {
        __syncthreads();
        if (tid < QP_ROWS * 16) {
            int row = tid >> 4, c4 = tid & 15;
            float4 v = *(const float4*)&W[(size_t)(dbase + row) * DIM + kb + c4 * 4];
            sW[row][c4*4+0]=v.x; sW[row][c4*4+1]=v.y; sW[row][c4*4+2]=v.z; sW[row][c4*4+3]=v.w;
        }
        #pragma unroll
        for (int i = 0; i < 4; i++) {
            int idx = tid + i * 256;
            int row = idx >> 4, c4 = idx & 15;
            float4 v = *(const float4*)&query[(size_t)row * DIM + kb + c4 * 4];
            sQ[row][c4*4+0]=v.x; sQ[row][c4*4+1]=v.y; sQ[row][c4*4+2]=v.z; sQ[row][c4*4+3]=v.w;
        }
        __syncthreads();
        #pragma unroll 8
        for (int k = 0; k < QP_KC; k++) {
            float qv = sQ[q][k];
            #pragma unroll
            for (int i = 0; i < 2; i++) acc[i] += sW[dg * 2 + i][k] * qv;
        }
    }

    unsigned char* qsw = (unsigned char*)g_qswh4;
    #pragma unroll
    for (int i = 0; i < 2; i++) {
        int d = dbase + dg * 2 + i;
        float val = acc[i] + bias[d];
        g_qf[(size_t)q * DIM + d] = val;                 // exact fp32 for pass 2
        __half h = __float2half_rn(val);
        int cch = d >> 6;
        int rr  = d & 63;
        uint32_t off = SW128((uint32_t)(rr * 128 + q * 2));
        *(unsigned short*)(qsw + cch * B_SPLIT + off) = __half_as_ushort(h);
    }
}

// ---------------- kernel 2 (pass 1): hh-only scores + per-block top-16 ----------------
__global__ __launch_bounds__(NTHREADS, 2) void score_topk_kernel(
    const float* __restrict__ emb, int ndocs, int ntiles)
{
    extern __shared__ char dynsmem[];
    __shared__ float topv[QN][TOPC];
    __shared__ int   topi[QN][TOPC];

    int tid  = threadIdx.x;
    int lane = tid & 31;
    int w    = tid >> 5;          // m-group: rows [w*16, w*16+16)
    int gr   = lane >> 2;
    int gc   = (lane & 3) * 2;
    int l15  = lane & 15;
    int lh8  = (lane >> 4) * 8;

    uint32_t raw  = smem_u32(dynsmem);
    uint32_t base = (raw + 1023) & ~1023u;
    char*    pool = dynsmem + (base - raw);
    float*   stage = (float*)(pool + OFF_STAGE);

    if (tid < QN) {
        #pragma unroll
        for (int j = 0; j < TOPC; j++) { topv[tid][j] = -FLT_MAX; topi[tid][j] = 0x7fffffff; }
    }

    float acc[8][4];
    #pragma unroll
    for (int ni = 0; ni < 8; ni++)
        #pragma unroll
        for (int r = 0; r < 4; r++) acc[ni][r] = 0.f;

    int t = blockIdx.x;
    if (t < ntiles) {
        issue_B(base, 0, tid);
        asm volatile("cp.async.commit_group;" ::: "memory");
        float2 f[4];
        ldgA(f, emb, t * TILE_M, 0, ndocs, w, gr, gc);

        int c = 0, p = 0;
        while (true) {
            int cn = c + 1, tn = t;
            bool more = true;
            if (cn == NCHUNK) { cn = 0; tn = t + gridDim.x; more = (tn < ntiles); }

            asm volatile("cp.async.wait_group 0;" ::: "memory");
            __syncthreads();                        // B buf p visible

            if (more) issue_B(base + (uint32_t)((p ^ 1) * B_SPLIT), cn, tid);
            asm volatile("cp.async.commit_group;" ::: "memory");

            // L2 prefetch next chunk's A rows
            if (more) {
                int row  = tid >> 1;
                int gdoc = tn * TILE_M + row;
                if (gdoc < ndocs) {
                    const float* pf = emb + (size_t)gdoc * DIM + cn * CHUNK_K + (tid & 1) * 32;
                    asm volatile("prefetch.global.L2 [%0];" :: "l"(pf));
                }
            }

            uint32_t bufB = base + (uint32_t)(p * B_SPLIT);

            #pragma unroll
            for (int ks = 0; ks < KSTEPS; ks++) {
                uint32_t Ahi[4];
                packA(f, Ahi);
                if (ks < KSTEPS - 1)
                    ldgA(f, emb, t * TILE_M, c * CHUNK_K + (ks + 1) * 16, ndocs, w, gr, gc);
                else if (more)
                    ldgA(f, emb, tn * TILE_M, cn * CHUNK_K, ndocs, w, gr, gc);

                uint32_t Bf[16];
                #pragma unroll
                for (int nb = 0; nb < 4; nb++)
                    ldsm_x4_t(&Bf[nb * 4],
                        bufB + SW128((uint32_t)((ks * 16 + l15) * 128 + (nb * 16 + lh8) * 2)));

                #pragma unroll
                for (int ni = 0; ni < 8; ni++)
                    mma_fp16(acc[ni], Ahi, &Bf[ni * 2]);
            }

            if (c == NCHUNK - 1) {
                #pragma unroll
                for (int ni = 0; ni < 8; ni++) {
                    int row = w * 16 + gr;
                    int col = ni * 8 + gc;
                    *(float2*)&stage[row * STAGE_STRIDE + col] =
                        make_float2(acc[ni][0], acc[ni][1]);
                    *(float2*)&stage[(row + 8) * STAGE_STRIDE + col] =
                        make_float2(acc[ni][2], acc[ni][3]);
                }
                __syncthreads();
                if (tid < QN) {
                    float* tv = topv[tid];
                    int*   ti = topi[tid];
                    int docbase = t * TILE_M;
                    int dmax = ndocs - docbase;
                    if (dmax > TILE_M) dmax = TILE_M;
                    for (int dl = 0; dl < dmax; dl++) {
                        float s = stage[dl * STAGE_STRIDE + tid];
                        if (s > tv[TOPC - 1]) topk_insert<TOPC>(tv, ti, s, docbase + dl);
                    }
                }
                #pragma unroll
                for (int ni = 0; ni < 8; ni++)
                    #pragma unroll
                    for (int r = 0; r < 4; r++) acc[ni][r] = 0.f;
            }

            if (!more) break;
            t = tn; c = cn; p ^= 1;
        }
    }

    __syncthreads();
    if (tid < QN) {
        #pragma unroll
        for (int j = 0; j < TOPC; j++) {
            size_t o = ((size_t)blockIdx.x * QN + tid) * TOPC + j;
            g_cand_val[o] = topv[tid][j];
            g_cand_idx[o] = topi[tid][j];
        }
    }
}

// ---------------- kernel 3 (pass 2): threshold + exact fp32 re-rank -> top-5 ----------------
#define MAXCAND 128
__global__ __launch_bounds__(256) void final_topk_kernel(
    float* __restrict__ out, const float* __restrict__ emb, int ndocs)
{
    __shared__ float sv[256 * TOPK];
    __shared__ int   si[256 * TOPK];
    __shared__ float s_thresh;
    __shared__ int   s_cnt;
    __shared__ int   cl[MAXCAND];
    __shared__ float ce[MAXCAND];

    int q    = blockIdx.x;
    int tid  = threadIdx.x;
    int lane = tid & 31;
    int wp   = tid >> 5;
    const int NC = NBLOCKS * TOPC;   // 4864 candidates per query

    // 1) per-thread top-5 of s_hh -> global T5_hh
    float lv[TOPK]; int li[TOPK];
    #pragma unroll
    for (int j = 0; j < TOPK; j++) { lv[j] = -FLT_MAX; li[j] = 0x7fffffff; }
    for (int e = tid; e < NC; e += 256) {
        int blk = e / TOPC, slot = e % TOPC;
        size_t o = ((size_t)blk * QN + q) * TOPC + slot;
        topk_insert<TOPK>(lv, li, g_cand_val[o], g_cand_idx[o]);
    }
    #pragma unroll
    for (int j = 0; j < TOPK; j++) { sv[tid * TOPK + j] = lv[j]; si[tid * TOPK + j] = li[j]; }
    if (tid == 0) s_cnt = 0;
    __syncthreads();
    if (tid == 0) {
        float fv[TOPK]; int fi[TOPK];
        #pragma unroll
        for (int j = 0; j < TOPK; j++) { fv[j] = -FLT_MAX; fi[j] = 0x7fffffff; }
        for (int e = 0; e < 256 * TOPK; e++)
            topk_insert<TOPK>(fv, fi, sv[e], si[e]);
        s_thresh = fv[TOPK - 1] - MARGIN;
    }
    __syncthreads();
    float thresh = s_thresh;

    // 2) collect survivors (deterministic SET; order immaterial)
    for (int e = tid; e < NC; e += 256) {
        int blk = e / TOPC, slot = e % TOPC;
        size_t o = ((size_t)blk * QN + q) * TOPC + slot;
        float v = g_cand_val[o];
        int   ix = g_cand_idx[o];
        if (v >= thresh && ix < ndocs) {
            int pos = atomicAdd(&s_cnt, 1);
            if (pos < MAXCAND) cl[pos] = ix;
        }
    }
    __syncthreads();
    int nc = s_cnt < MAXCAND ? s_cnt : MAXCAND;

    // 3) exact fp32 re-score: one warp per candidate
    const float* qf = g_qf + (size_t)q * DIM;
    for (int ci = wp; ci < nc; ci += 8) {
        const float* dr = emb + (size_t)cl[ci] * DIM;
        float s = 0.f;
        for (int d = lane; d < DIM; d += 32)
            s += __ldg(qf + d) * __ldg(dr + d);
        #pragma unroll
        for (int off = 16; off > 0; off >>= 1)
            s += __shfl_xor_sync(0xFFFFFFFF, s, off);
        if (lane == 0) ce[ci] = s;
    }
    __syncthreads();

    // 4) exact top-5 (ties -> lower index), write float indices
    if (tid == 0) {
        float fv[TOPK]; int fi[TOPK];
        #pragma unroll
        for (int j = 0; j < TOPK; j++) { fv[j] = -FLT_MAX; fi[j] = 0x7fffffff; }
        for (int ci = 0; ci < nc; ci++)
            topk_insert<TOPK>(fv, fi, ce[ci], cl[ci]);
        #pragma unroll
        for (int j = 0; j < TOPK; j++) out[q * TOPK + j] = (float)fi[j];
    }
}

// ---------------- launch ----------------
// Inputs identified BY ELEMENT COUNT:
//   b = 768, query = 49152, W = 589824, block_emb = largest, top_k scalar ignored (TOPK=5 per out_size).
extern "C" void kernel_launch(void* const* d_in, const int* in_sizes, int n_in,
                              void* d_out, int out_size)
{
    const float *query = nullptr, *W = nullptr, *bias = nullptr, *emb = nullptr;
    int ndocs = 0;
    for (int i = 0; i < n_in; i++) {
        int sz = in_sizes[i];
        if      (sz == DIM)        bias  = (const float*)d_in[i];
        else if (sz == QN * DIM)   query = (const float*)d_in[i];
        else if (sz == DIM * DIM)  W     = (const float*)d_in[i];
        else if (sz >  DIM * DIM) { emb  = (const float*)d_in[i]; ndocs = sz / DIM; }
    }
    if (!query || !W || !bias || !emb || ndocs <= 0) return;

    int ntiles = (ndocs + TILE_M - 1) / TILE_M;

    cudaFuncSetAttribute(score_topk_kernel, cudaFuncAttributeMaxDynamicSharedMemorySize, SMEM_DYN);

    qproj_kernel<<<DIM / QP_ROWS, 256>>>(query, W, bias);
    score_topk_kernel<<<NBLOCKS, NTHREADS, SMEM_DYN>>>(emb, ndocs, ntiles);
    final_topk_kernel<<<QN, 256>>>((float*)d_out, emb, ndocs);
}

// round 17
// speedup vs baseline: 1.0322x; 1.0322x over previous
#include <cuda_runtime.h>
#include <cuda_fp16.h>
#include <cfloat>
#include <cstdint>

#define DIM      768
#define QN       64
#define TILE_M   128
#define CHUNK_K  64
#define NCHUNK   (DIM / CHUNK_K)     // 12
#define KSTEPS   (CHUNK_K / 16)      // 4
#define NTHREADS 256
#define NBLOCKS  304                 // 2 per SM x 152 SMs
#define TOPC     16                  // pass-1 per-block candidates per query
#define TOPK     5
#define MARGIN   4.0f                // > 2x hard bound on |s3term - s_hh|

// ---- smem layout: [B buf0 8KB][B buf1 8KB][stage 34.8KB] ----
#define B_SPLIT   8192                          // hi-split tile: 64 k-rows x 128B SW128
#define OFF_STAGE (2 * B_SPLIT)                 // 16384
#define STAGE_STRIDE 68
#define STAGE_BYTES  (TILE_M * STAGE_STRIDE * 4)   // 34816
#define SMEM_DYN  (OFF_STAGE + STAGE_BYTES + 1024) // 52224/CTA; 2 CTAs ~ 104KB

// ---------------- device scratch (no allocations allowed) ----------------
__device__ uint4 g_qswh4[NCHUNK * B_SPLIT / 16];   // hi-split pre-swizzled per-chunk images
__device__ float g_qf[QN * DIM];                   // exact fp32 projected queries (pass 2)
__device__ float g_cand_val[NBLOCKS * QN * TOPC];
__device__ int   g_cand_idx[NBLOCKS * QN * TOPC];

// ---------------- helpers ----------------
__device__ __forceinline__ uint32_t smem_u32(const void* p) {
    uint32_t a;
    asm("{ .reg .u64 t; cvta.to.shared.u64 t, %1; cvt.u32.u64 %0, t; }" : "=r"(a) : "l"(p));
    return a;
}
#define SW128(off) ((off) ^ (((off) >> 3) & 0x70))

__device__ __forceinline__ void ldsm_x4_t(uint32_t* r, uint32_t addr) {
    asm volatile("ldmatrix.sync.aligned.m8n8.x4.trans.shared.b16 {%0,%1,%2,%3}, [%4];"
        : "=r"(r[0]), "=r"(r[1]), "=r"(r[2]), "=r"(r[3]) : "r"(addr));
}
__device__ __forceinline__ void mma_fp16(float* d, const uint32_t* a, const uint32_t* b) {
    asm volatile("mma.sync.aligned.m16n8k16.row.col.f32.f16.f16.f32 "
        "{%0,%1,%2,%3}, {%4,%5,%6,%7}, {%8,%9}, {%0,%1,%2,%3};"
        : "+f"(d[0]), "+f"(d[1]), "+f"(d[2]), "+f"(d[3])
        : "r"(a[0]), "r"(a[1]), "r"(a[2]), "r"(a[3]), "r"(b[0]), "r"(b[1]));
}

// strict ordering: higher value wins; ties -> lower index (matches lax.top_k)
__device__ __forceinline__ bool better(float av, int ai, float bv, int bi) {
    return (av > bv) || (av == bv && ai < bi);
}
template <int K>
__device__ __forceinline__ void topk_insert(float* tv, int* ti, float s, int idx) {
    if (!better(s, idx, tv[K - 1], ti[K - 1])) return;
    int pos = K - 1;
    #pragma unroll
    for (int it = 0; it < K - 1; it++) {
        if (pos > 0 && better(s, idx, tv[pos - 1], ti[pos - 1])) {
            tv[pos] = tv[pos - 1]; ti[pos] = ti[pos - 1]; pos--;
        }
    }
    tv[pos] = s; ti[pos] = idx;
}

// issue cp.async for one hi-split B chunk image (8KB, 2x16B per thread)
__device__ __forceinline__ void issue_B(uint32_t bufS, int chunk, int tid) {
    const char* src = (const char*)g_qswh4 + (size_t)chunk * B_SPLIT;
    #pragma unroll
    for (int j = 0; j < 2; j++) {
        uint32_t dst = bufS + (uint32_t)((tid + j * NTHREADS) * 16);
        asm volatile("cp.async.ca.shared.global [%0], [%1], 16;"
                     :: "r"(dst), "l"(src + (tid + j * NTHREADS) * 16));
    }
}

// per-lane A fragment fp32 load: rows {r0,r0+8}, col pairs {c0,c0+8}
__device__ __forceinline__ void ldgA(float2* f, const float* __restrict__ emb,
                                     int docbase, int k0, int ndocs,
                                     int w, int gr, int gc) {
    int r0 = docbase + w * 16 + gr;
    int r1 = r0 + 8;
    const float* p0 = emb + (size_t)r0 * DIM + k0 + gc;
    const float* p1 = emb + (size_t)r1 * DIM + k0 + gc;
    float2 z = make_float2(0.f, 0.f);
    f[0] = (r0 < ndocs) ? __ldcg((const float2*)p0)       : z;
    f[1] = (r1 < ndocs) ? __ldcg((const float2*)p1)       : z;
    f[2] = (r0 < ndocs) ? __ldcg((const float2*)(p0 + 8)) : z;
    f[3] = (r1 < ndocs) ? __ldcg((const float2*)(p1 + 8)) : z;
}
// pack fp32 fragment pairs -> hi fp16 fragment regs (rn)
__device__ __forceinline__ void packA(const float2* f, uint32_t* Ahi) {
    #pragma unroll
    for (int j = 0; j < 4; j++) {
        __half2 h = __floats2half2_rn(f[j].x, f[j].y);
        Ahi[j] = *(const uint32_t*)&h;
    }
}

// ---------------- kernel 1: q = query @ W^T + b -> fp32 q + hi-split swizzled tiles ----------------
#define QP_KC 64
#define QP_ROWS 8
__global__ __launch_bounds__(256) void qproj_kernel(
    const float* __restrict__ query, const float* __restrict__ W, const float* __restrict__ bias)
{
    __shared__ float sW[QP_ROWS][QP_KC];
    __shared__ float sQ[QN][QP_KC + 1];

    int tid = threadIdx.x;
    int dbase = blockIdx.x * QP_ROWS;
    int q  = tid & 63;
    int dg = tid >> 6;

    float acc[2] = {0.f, 0.f};

    for (int kb = 0; kb < DIM; kb += QP_KC) {
        __syncthreads();
        if (tid < QP_ROWS * 16) {
            int row = tid >> 4, c4 = tid & 15;
            float4 v = *(const float4*)&W[(size_t)(dbase + row) * DIM + kb + c4 * 4];
            sW[row][c4*4+0]=v.x; sW[row][c4*4+1]=v.y; sW[row][c4*4+2]=v.z; sW[row][c4*4+3]=v.w;
        }
        #pragma unroll
        for (int i = 0; i < 4; i++) {
            int idx = tid + i * 256;
            int row = idx >> 4, c4 = idx & 15;
            float4 v = *(const float4*)&query[(size_t)row * DIM + kb + c4 * 4];
            sQ[row][c4*4+0]=v.x; sQ[row][c4*4+1]=v.y; sQ[row][c4*4+2]=v.z; sQ[row][c4*4+3]=v.w;
        }
        __syncthreads();
        #pragma unroll 8
        for (int k = 0; k < QP_KC; k++) {
            float qv = sQ[q][k];
            #pragma unroll
            for (int i = 0; i < 2; i++) acc[i] += sW[dg * 2 + i][k] * qv;
        }
    }

    unsigned char* qsw = (unsigned char*)g_qswh4;
    #pragma unroll
    for (int i = 0; i < 2; i++) {
        int d = dbase + dg * 2 + i;
        float val = acc[i] + bias[d];
        g_qf[(size_t)q * DIM + d] = val;                 // exact fp32 for pass 2
        __half h = __float2half_rn(val);
        int cch = d >> 6;
        int rr  = d & 63;
        uint32_t off = SW128((uint32_t)(rr * 128 + q * 2));
        *(unsigned short*)(qsw + cch * B_SPLIT + off) = __half_as_ushort(h);
    }
}

// ---------------- kernel 2 (pass 1): hh-only scores, A prefetched a FULL CHUNK ahead ----------------
__global__ __launch_bounds__(NTHREADS, 2) void score_topk_kernel(
    const float* __restrict__ emb, int ndocs, int ntiles)
{
    extern __shared__ char dynsmem[];
    __shared__ float topv[QN][TOPC];
    __shared__ int   topi[QN][TOPC];

    int tid  = threadIdx.x;
    int lane = tid & 31;
    int w    = tid >> 5;          // m-group: rows [w*16, w*16+16)
    int gr   = lane >> 2;
    int gc   = (lane & 3) * 2;
    int l15  = lane & 15;
    int lh8  = (lane >> 4) * 8;

    uint32_t raw  = smem_u32(dynsmem);
    uint32_t base = (raw + 1023) & ~1023u;
    char*    pool = dynsmem + (base - raw);
    float*   stage = (float*)(pool + OFF_STAGE);

    if (tid < QN) {
        #pragma unroll
        for (int j = 0; j < TOPC; j++) { topv[tid][j] = -FLT_MAX; topi[tid][j] = 0x7fffffff; }
    }

    float acc[8][4];
    #pragma unroll
    for (int ni = 0; ni < 8; ni++)
        #pragma unroll
        for (int r = 0; r < 4; r++) acc[ni][r] = 0.f;

    int t = blockIdx.x;
    if (t < ntiles) {
        issue_B(base, 0, tid);
        asm volatile("cp.async.commit_group;" ::: "memory");

        // prologue: A fragments for the ENTIRE first chunk (4 ks x 4 float2 = 32 regs)
        float2 fA[16];
        #pragma unroll
        for (int ks = 0; ks < KSTEPS; ks++)
            ldgA(fA + ks * 4, emb, t * TILE_M, ks * 16, ndocs, w, gr, gc);

        int c = 0, p = 0;
        while (true) {
            int cn = c + 1, tn = t;
            bool more = true;
            if (cn == NCHUNK) { cn = 0; tn = t + gridDim.x; more = (tn < ntiles); }

            asm volatile("cp.async.wait_group 0;" ::: "memory");
            __syncthreads();                        // B buf p visible

            if (more) issue_B(base + (uint32_t)((p ^ 1) * B_SPLIT), cn, tid);
            asm volatile("cp.async.commit_group;" ::: "memory");

            uint32_t bufB = base + (uint32_t)(p * B_SPLIT);

            #pragma unroll
            for (int ks = 0; ks < KSTEPS; ks++) {
                uint32_t Ahi[4];
                packA(fA + ks * 4, Ahi);
                // reload this slot with NEXT CHUNK's same-ks fragment:
                // consumed one full chunk later -> ~full chunk of latency distance
                if (more)
                    ldgA(fA + ks * 4, emb, tn * TILE_M, cn * CHUNK_K + ks * 16,
                         ndocs, w, gr, gc);

                uint32_t Bf[16];
                #pragma unroll
                for (int nb = 0; nb < 4; nb++)
                    ldsm_x4_t(&Bf[nb * 4],
                        bufB + SW128((uint32_t)((ks * 16 + l15) * 128 + (nb * 16 + lh8) * 2)));

                #pragma unroll
                for (int ni = 0; ni < 8; ni++)
                    mma_fp16(acc[ni], Ahi, &Bf[ni * 2]);
            }

            if (c == NCHUNK - 1) {
                #pragma unroll
                for (int ni = 0; ni < 8; ni++) {
                    int row = w * 16 + gr;
                    int col = ni * 8 + gc;
                    *(float2*)&stage[row * STAGE_STRIDE + col] =
                        make_float2(acc[ni][0], acc[ni][1]);
                    *(float2*)&stage[(row + 8) * STAGE_STRIDE + col] =
                        make_float2(acc[ni][2], acc[ni][3]);
                }
                __syncthreads();
                if (tid < QN) {
                    float* tv = topv[tid];
                    int*   ti = topi[tid];
                    int docbase = t * TILE_M;
                    int dmax = ndocs - docbase;
                    if (dmax > TILE_M) dmax = TILE_M;
                    for (int dl = 0; dl < dmax; dl++) {
                        float s = stage[dl * STAGE_STRIDE + tid];
                        if (s > tv[TOPC - 1]) topk_insert<TOPC>(tv, ti, s, docbase + dl);
                    }
                }
                #pragma unroll
                for (int ni = 0; ni < 8; ni++)
                    #pragma unroll
                    for (int r = 0; r < 4; r++) acc[ni][r] = 0.f;
            }

            if (!more) break;
            t = tn; c = cn; p ^= 1;
        }
    }

    __syncthreads();
    if (tid < QN) {
        #pragma unroll
        for (int j = 0; j < TOPC; j++) {
            size_t o = ((size_t)blockIdx.x * QN + tid) * TOPC + j;
            g_cand_val[o] = topv[tid][j];
            g_cand_idx[o] = topi[tid][j];
        }
    }
}

// ---------------- kernel 3 (pass 2): threshold + exact fp32 re-rank -> top-5 ----------------
#define MAXCAND 128
__global__ __launch_bounds__(256) void final_topk_kernel(
    float* __restrict__ out, const float* __restrict__ emb, int ndocs)
{
    __shared__ float sv[256 * TOPK];
    __shared__ int   si[256 * TOPK];
    __shared__ float s_thresh;
    __shared__ int   s_cnt;
    __shared__ int   cl[MAXCAND];
    __shared__ float ce[MAXCAND];

    int q    = blockIdx.x;
    int tid  = threadIdx.x;
    int lane = tid & 31;
    int wp   = tid >> 5;
    const int NC = NBLOCKS * TOPC;   // 4864 candidates per query

    // 1) per-thread top-5 of s_hh -> global T5_hh
    float lv[TOPK]; int li[TOPK];
    #pragma unroll
    for (int j = 0; j < TOPK; j++) { lv[j] = -FLT_MAX; li[j] = 0x7fffffff; }
    for (int e = tid; e < NC; e += 256) {
        int blk = e / TOPC, slot = e % TOPC;
        size_t o = ((size_t)blk * QN + q) * TOPC + slot;
        topk_insert<TOPK>(lv, li, g_cand_val[o], g_cand_idx[o]);
    }
    #pragma unroll
    for (int j = 0; j < TOPK; j++) { sv[tid * TOPK + j] = lv[j]; si[tid * TOPK + j] = li[j]; }
    if (tid == 0) s_cnt = 0;
    __syncthreads();
    if (tid == 0) {
        float fv[TOPK]; int fi[TOPK];
        #pragma unroll
        for (int j = 0; j < TOPK; j++) { fv[j] = -FLT_MAX; fi[j] = 0x7fffffff; }
        for (int e = 0; e < 256 * TOPK; e++)
            topk_insert<TOPK>(fv, fi, sv[e], si[e]);
        s_thresh = fv[TOPK - 1] - MARGIN;
    }
    __syncthreads();
    float thresh = s_thresh;

    // 2) collect survivors (deterministic SET; order immaterial)
    for (int e = tid; e < NC; e += 256) {
        int blk = e / TOPC, slot = e % TOPC;
        size_t o = ((size_t)blk * QN + q) * TOPC + slot;
        float v = g_cand_val[o];
        int   ix = g_cand_idx[o];
        if (v >= thresh && ix < ndocs) {
            int pos = atomicAdd(&s_cnt, 1);
            if (pos < MAXCAND) cl[pos] = ix;
        }
    }
    __syncthreads();
    int nc = s_cnt < MAXCAND ? s_cnt : MAXCAND;

    // 3) exact fp32 re-score: one warp per candidate
    const float* qf = g_qf + (size_t)q * DIM;
    for (int ci = wp; ci < nc; ci += 8) {
        const float* dr = emb + (size_t)cl[ci] * DIM;
        float s = 0.f;
        for (int d = lane; d < DIM; d += 32)
            s += __ldg(qf + d) * __ldg(dr + d);
        #pragma unroll
        for (int off = 16; off > 0; off >>= 1)
            s += __shfl_xor_sync(0xFFFFFFFF, s, off);
        if (lane == 0) ce[ci] = s;
    }
    __syncthreads();

    // 4) exact top-5 (ties -> lower index), write float indices
    if (tid == 0) {
        float fv[TOPK]; int fi[TOPK];
        #pragma unroll
        for (int j = 0; j < TOPK; j++) { fv[j] = -FLT_MAX; fi[j] = 0x7fffffff; }
        for (int ci = 0; ci < nc; ci++)
            topk_insert<TOPK>(fv, fi, ce[ci], cl[ci]);
        #pragma unroll
        for (int j = 0; j < TOPK; j++) out[q * TOPK + j] = (float)fi[j];
    }
}

// ---------------- launch ----------------
// Inputs identified BY ELEMENT COUNT:
//   b = 768, query = 49152, W = 589824, block_emb = largest, top_k scalar ignored (TOPK=5 per out_size).
extern "C" void kernel_launch(void* const* d_in, const int* in_sizes, int n_in,
                              void* d_out, int out_size)
{
    const float *query = nullptr, *W = nullptr, *bias = nullptr, *emb = nullptr;
    int ndocs = 0;
    for (int i = 0; i < n_in; i++) {
        int sz = in_sizes[i];
        if      (sz == DIM)        bias  = (const float*)d_in[i];
        else if (sz == QN * DIM)   query = (const float*)d_in[i];
        else if (sz == DIM * DIM)  W     = (const float*)d_in[i];
        else if (sz >  DIM * DIM) { emb  = (const float*)d_in[i]; ndocs = sz / DIM; }
    }
    if (!query || !W || !bias || !emb || ndocs <= 0) return;

    int ntiles = (ndocs + TILE_M - 1) / TILE_M;

    cudaFuncSetAttribute(score_topk_kernel, cudaFuncAttributeMaxDynamicSharedMemorySize, SMEM_DYN);

    qproj_kernel<<<DIM / QP_ROWS, 256>>>(query, W, bias);
    score_topk_kernel<<<NBLOCKS, NTHREADS, SMEM_DYN>>>(emb, ndocs, ntiles);
    final_topk_kernel<<<QN, 256>>>((float*)d_out, emb, ndocs);
}